// round 1
// baseline (speedup 1.0000x reference)
#include <cuda_runtime.h>
#include <cuda_bf16.h>

#define N_SRC0 286000
#define N_DST0 11000
#define N_E0   275000
#define N_DST1 1000
#define N_E1   10000
#define F_IN   602
#define F_HID  256
#define F_OUT  41
#define K_TOT0 (2 * F_IN)   // 1204 : concatenated [x | agg_mean] K dim

// ---------------- scratch (static device globals; no allocation) -------------
__device__ float g_agg0[(size_t)N_DST0 * F_IN];   // 26.5 MB
__device__ float g_cnt0[N_DST0];
__device__ float g_h   [(size_t)N_DST0 * F_HID];  // 11.3 MB
__device__ float g_agg1[(size_t)N_DST1 * F_HID];  // 1 MB
__device__ float g_cnt1[N_DST1];

// ---------------- zero all scratch -------------------------------------------
__global__ void k_zero_scratch() {
    int i  = blockIdx.x * blockDim.x + threadIdx.x;
    int st = gridDim.x * blockDim.x;
    for (int j = i; j < N_DST0 * F_IN;  j += st) g_agg0[j] = 0.f;
    for (int j = i; j < N_DST0;         j += st) g_cnt0[j] = 0.f;
    for (int j = i; j < N_DST1 * F_HID; j += st) g_agg1[j] = 0.f;
    for (int j = i; j < N_DST1;         j += st) g_cnt1[j] = 0.f;
}

// ---------------- layer-0 scatter: one warp per edge --------------------------
__global__ void k_scatter0(const float* __restrict__ x,
                           const int* __restrict__ src,
                           const int* __restrict__ dst) {
    int gthread = blockIdx.x * blockDim.x + threadIdx.x;
    int warp = gthread >> 5;
    int lane = threadIdx.x & 31;
    if (warp >= N_E0) return;
    int s = src[warp];
    int d = dst[warp];
    const float* xs = x      + (size_t)s * F_IN;
    float*       ag = g_agg0 + (size_t)d * F_IN;
    #pragma unroll 4
    for (int f = lane; f < F_IN; f += 32)
        atomicAdd(ag + f, __ldg(xs + f));
    if (lane == 0) atomicAdd(&g_cnt0[d], 1.f);
}

// ---------------- divide by count (mean) --------------------------------------
__global__ void k_scale0() {
    int i  = blockIdx.x * blockDim.x + threadIdx.x;
    int st = gridDim.x * blockDim.x;
    for (int j = i; j < N_DST0 * F_IN; j += st) {
        int row = j / F_IN;
        float c = g_cnt0[row];
        g_agg0[j] *= 1.f / fmaxf(c, 1.f);
    }
}

// ---------------- layer-0 fused GEMM + bias + relu ----------------------------
// h = relu([x[:N_DST0] | agg_mean] @ [Wself0; Wneigh0] + b0)
// M=11000, N=256, K=1204. 64x64 tile, BK=16, 256 threads, 4x4 per thread.
__global__ void __launch_bounds__(256)
k_gemm0(const float* __restrict__ x,
        const float* __restrict__ Wself,
        const float* __restrict__ Wneigh,
        const float* __restrict__ b0) {
    const int BM = 64, BN = 64, BK = 16;
    __shared__ float As[BK][BM + 1];
    __shared__ float Bs[BK][BN];

    int tid = threadIdx.x;
    int tx = tid & 15;        // 0..15 -> col group
    int ty = tid >> 4;        // 0..15 -> row group
    int rowBase = blockIdx.y * BM;
    int colBase = blockIdx.x * BN;

    float acc[4][4] = {};

    for (int k0 = 0; k0 < K_TOT0; k0 += BK) {
        // --- load A tile (virtual concat of x and agg0), coalesced along k ---
        #pragma unroll
        for (int l = 0; l < 4; l++) {
            int idx = tid + 256 * l;        // 0..1023
            int kk  = idx & (BK - 1);       // fast dim -> k (coalesced)
            int m   = idx >> 4;
            int grow = rowBase + m;
            int gk   = k0 + kk;
            float v = 0.f;
            if (grow < N_DST0) {
                if (gk < F_IN)
                    v = __ldg(&x[(size_t)grow * F_IN + gk]);
                else if (gk < K_TOT0)
                    v = g_agg0[(size_t)grow * F_IN + (gk - F_IN)];
            }
            As[kk][m] = v;
        }
        // --- load B tile (virtual concat of Wself/Wneigh), coalesced along n ---
        #pragma unroll
        for (int l = 0; l < 4; l++) {
            int idx = tid + 256 * l;        // 0..1023
            int col = idx & (BN - 1);       // fast dim -> n (coalesced)
            int kk  = idx >> 6;
            int gk  = k0 + kk;
            int gcol = colBase + col;
            float v = 0.f;
            if (gk < F_IN)
                v = __ldg(&Wself[(size_t)gk * F_HID + gcol]);
            else if (gk < K_TOT0)
                v = __ldg(&Wneigh[(size_t)(gk - F_IN) * F_HID + gcol]);
            Bs[kk][col] = v;
        }
        __syncthreads();

        #pragma unroll
        for (int k = 0; k < BK; k++) {
            float a[4], b[4];
            #pragma unroll
            for (int i = 0; i < 4; i++) a[i] = As[k][ty * 4 + i];
            #pragma unroll
            for (int j = 0; j < 4; j++) b[j] = Bs[k][tx * 4 + j];
            #pragma unroll
            for (int i = 0; i < 4; i++)
                #pragma unroll
                for (int j = 0; j < 4; j++)
                    acc[i][j] += a[i] * b[j];
        }
        __syncthreads();
    }

    #pragma unroll
    for (int i = 0; i < 4; i++) {
        int r = rowBase + ty * 4 + i;
        if (r >= N_DST0) continue;
        #pragma unroll
        for (int j = 0; j < 4; j++) {
            int c = colBase + tx * 4 + j;
            float v = acc[i][j] + __ldg(&b0[c]);
            g_h[(size_t)r * F_HID + c] = fmaxf(v, 0.f);
        }
    }
}

// ---------------- layer-1 scatter: one warp per edge ---------------------------
__global__ void k_scatter1(const int* __restrict__ src,
                           const int* __restrict__ dst) {
    int gthread = blockIdx.x * blockDim.x + threadIdx.x;
    int warp = gthread >> 5;
    int lane = threadIdx.x & 31;
    if (warp >= N_E1) return;
    int s = src[warp];
    int d = dst[warp];
    const float* hs = g_h    + (size_t)s * F_HID;
    float*       ag = g_agg1 + (size_t)d * F_HID;
    #pragma unroll
    for (int f = lane; f < F_HID; f += 32)
        atomicAdd(ag + f, hs[f]);
    if (lane == 0) atomicAdd(&g_cnt1[d], 1.f);
}

__global__ void k_scale1() {
    int i  = blockIdx.x * blockDim.x + threadIdx.x;
    int st = gridDim.x * blockDim.x;
    for (int j = i; j < N_DST1 * F_HID; j += st) {
        int row = j >> 8;
        float c = g_cnt1[row];
        g_agg1[j] *= 1.f / fmaxf(c, 1.f);
    }
}

// ---------------- output GEMM: out = h[:1000]@Wself1 + agg1@Wneigh1 + b1 ------
__global__ void k_out(const float* __restrict__ Wself1,
                      const float* __restrict__ Wneigh1,
                      const float* __restrict__ b1,
                      float* __restrict__ out) {
    int idx = blockIdx.x * blockDim.x + threadIdx.x;
    if (idx >= N_DST1 * F_OUT) return;
    int row = idx / F_OUT;
    int col = idx - row * F_OUT;
    const float* hr = g_h    + (size_t)row * F_HID;
    const float* ar = g_agg1 + (size_t)row * F_HID;
    float acc = __ldg(&b1[col]);
    #pragma unroll 4
    for (int k = 0; k < F_HID; k++) {
        acc += hr[k] * __ldg(&Wself1[k * F_OUT + col]);
        acc += ar[k] * __ldg(&Wneigh1[k * F_OUT + col]);
    }
    out[idx] = acc;
}

// ---------------- launch ------------------------------------------------------
extern "C" void kernel_launch(void* const* d_in, const int* in_sizes, int n_in,
                              void* d_out, int out_size) {
    const float* x      = (const float*)d_in[0];
    const float* Wself0 = (const float*)d_in[1];
    const float* Wneigh0= (const float*)d_in[2];
    const float* b0     = (const float*)d_in[3];
    const float* Wself1 = (const float*)d_in[4];
    const float* Wneigh1= (const float*)d_in[5];
    const float* b1     = (const float*)d_in[6];
    const int*   e0_src = (const int*)d_in[7];
    const int*   e0_dst = (const int*)d_in[8];
    const int*   e1_src = (const int*)d_in[9];
    const int*   e1_dst = (const int*)d_in[10];
    float* out = (float*)d_out;

    // 1. zero scratch
    k_zero_scratch<<<1024, 256>>>();

    // 2. layer-0 scatter-add (one warp per edge)
    {
        int warps = N_E0;
        int threads = 256;
        int blocks = (warps * 32 + threads - 1) / threads;
        k_scatter0<<<blocks, threads>>>(x, e0_src, e0_dst);
    }

    // 3. mean
    k_scale0<<<2048, 256>>>();

    // 4. fused layer-0 GEMM + relu
    {
        dim3 grid(F_HID / 64, (N_DST0 + 63) / 64);  // (4, 172)
        k_gemm0<<<grid, 256>>>(x, Wself0, Wneigh0, b0);
    }

    // 5. layer-1 scatter-add
    {
        int warps = N_E1;
        int threads = 256;
        int blocks = (warps * 32 + threads - 1) / threads;
        k_scatter1<<<blocks, threads>>>(e1_src, e1_dst);
    }

    // 6. mean
    k_scale1<<<256, 256>>>();

    // 7. output GEMM
    {
        int total = N_DST1 * F_OUT;
        k_out<<<(total + 255) / 256, 256>>>(Wself1, Wneigh1, b1, out);
    }
}

// round 2
// speedup vs baseline: 1.0097x; 1.0097x over previous
#include <cuda_runtime.h>
#include <cuda_bf16.h>

#define N_SRC0 286000
#define N_DST0 11000
#define N_E0   275000
#define N_DST1 1000
#define N_E1   10000
#define F_IN   602
#define F_HID  256
#define F_OUT  41

// ---------------- scratch (static device globals; no allocation) -------------
__device__ float g_agg0[(size_t)N_DST0 * F_IN + 16];   // ~26.5 MB (+pad)
__device__ float g_cnt0[N_DST0];
__device__ float g_h   [(size_t)N_DST0 * F_HID];       // 11.3 MB
__device__ float g_agg1[(size_t)N_DST1 * F_HID];       // 1 MB
__device__ float g_cnt1[N_DST1];

// ---------------- zero all scratch -------------------------------------------
__global__ void k_zero_scratch() {
    int i  = blockIdx.x * blockDim.x + threadIdx.x;
    int st = gridDim.x * blockDim.x;
    for (int j = i; j < N_DST0 * F_IN;  j += st) g_agg0[j] = 0.f;
    for (int j = i; j < N_DST0;         j += st) g_cnt0[j] = 0.f;
    for (int j = i; j < N_DST1 * F_HID; j += st) g_agg1[j] = 0.f;
    for (int j = i; j < N_DST1;         j += st) g_cnt1[j] = 0.f;
}

// ---------------- layer-0 scatter: one warp per edge (float2 gathers) --------
__global__ void k_scatter0(const float* __restrict__ x,
                           const int* __restrict__ src,
                           const int* __restrict__ dst) {
    int gthread = blockIdx.x * blockDim.x + threadIdx.x;
    int warp = gthread >> 5;
    int lane = threadIdx.x & 31;
    if (warp >= N_E0) return;
    int s = src[warp];
    int d = dst[warp];
    const float2* xs = (const float2*)(x      + (size_t)s * F_IN); // 8B aligned: 602*4 % 8 == 0
    float*        ag = g_agg0 + (size_t)d * F_IN;
    const int NF2 = F_IN / 2;  // 301
    #pragma unroll 4
    for (int f = lane; f < NF2; f += 32) {
        float2 v = __ldg(xs + f);
        atomicAdd(ag + 2*f,     v.x);
        atomicAdd(ag + 2*f + 1, v.y);
    }
    if (lane == 0) atomicAdd(&g_cnt0[d], 1.f);
}

// ---------------- divide by count (mean) --------------------------------------
__global__ void k_scale0() {
    int i  = blockIdx.x * blockDim.x + threadIdx.x;
    int st = gridDim.x * blockDim.x;
    for (int j = i; j < N_DST0 * F_IN; j += st) {
        int row = j / F_IN;
        float c = g_cnt0[row];
        g_agg0[j] *= 1.f / fmaxf(c, 1.f);
    }
}

// =============================================================================
// layer-0 fused GEMM + bias + relu, packed f32x2 FFMA
// h = relu([x[:N_DST0] | agg_mean] @ [Wself0; Wneigh0] + b0)
// M=11000, N=256, K=2x602. Tile: BM=64, BN=64, BK=16, 64 threads, 8x8 microtile
// accumulators packed pairwise along M into f32x2; B duplicated in smem so the
// broadcast operand loads as a ready (b,b) 64-bit register.
// =============================================================================

#define FMA2(d, a, b) \
    asm("fma.rn.f32x2 %0, %1, %2, %0;" : "+l"(d) : "l"(a), "l"(b))

__device__ __forceinline__ void ldA(float2* fa, const float* __restrict__ Aptr,
                                    int rowBase, int k0, int t) {
    #pragma unroll
    for (int l = 0; l < 8; l++) {
        int q  = t + 64 * l;          // 0..511 (64 rows x 8 float2)
        int m  = q >> 3;
        int kh = q & 7;
        int gk = k0 + kh * 2;
        int gm = rowBase + m;
        float2 v = make_float2(0.f, 0.f);
        if (gk < F_IN && gm < N_DST0)
            v = *reinterpret_cast<const float2*>(Aptr + (size_t)gm * F_IN + gk);
        fa[l] = v;
    }
}

__device__ __forceinline__ void stA(float (*As)[68], const float2* fa, int t) {
    #pragma unroll
    for (int l = 0; l < 8; l++) {
        int q  = t + 64 * l;
        int m  = q >> 3;
        int kh = q & 7;
        As[kh * 2    ][m] = fa[l].x;
        As[kh * 2 + 1][m] = fa[l].y;
    }
}

__device__ __forceinline__ void ldB(float4* fb, const float* __restrict__ Bptr,
                                    int colBase, int k0, int t) {
    #pragma unroll
    for (int l = 0; l < 4; l++) {
        int q  = t + 64 * l;          // 0..255 (16 k-rows x 16 float4)
        int n4 = q & 15;
        int kk = q >> 4;
        int gk = k0 + kk;
        float4 v = make_float4(0.f, 0.f, 0.f, 0.f);
        if (gk < F_IN)
            v = *reinterpret_cast<const float4*>(Bptr + (size_t)gk * F_HID + colBase + n4 * 4);
        fb[l] = v;
    }
}

__device__ __forceinline__ void stB(float (*Bs)[128], const float4* fb, int t) {
    #pragma unroll
    for (int l = 0; l < 4; l++) {
        int q  = t + 64 * l;
        int n4 = q & 15;
        int kk = q >> 4;
        float2* p = reinterpret_cast<float2*>(&Bs[kk][n4 * 8]);
        p[0] = make_float2(fb[l].x, fb[l].x);
        p[1] = make_float2(fb[l].y, fb[l].y);
        p[2] = make_float2(fb[l].z, fb[l].z);
        p[3] = make_float2(fb[l].w, fb[l].w);
    }
}

__global__ void __launch_bounds__(64, 6)
k_gemm0(const float* __restrict__ x,
        const float* __restrict__ Wself,
        const float* __restrict__ Wneigh,
        const float* __restrict__ b0) {
    __shared__ float As [2][16][68];    // padded stride 68: mild STS conflicts only
    __shared__ float Bs2[2][16][128];   // 64 cols duplicated -> 128 floats / k-row

    const int t  = threadIdx.x;
    const int tx = t & 7;               // 8 col groups * 8 cols
    const int ty = t >> 3;              // 8 row groups * 8 rows
    const int rowBase = blockIdx.y * 64;
    const int colBase = blockIdx.x * 64;

    unsigned long long acc[4][8];       // [row-pair][col] f32x2
    #pragma unroll
    for (int i = 0; i < 4; i++)
        #pragma unroll
        for (int j = 0; j < 8; j++) acc[i][j] = 0ull;

    const int TILES = 38;               // ceil(602/16)
    float2 fa[8];
    float4 fb[4];

    // prologue: tile 0 (pass 0: x / Wself)
    ldA(fa, x, rowBase, 0, t);
    ldB(fb, Wself, colBase, 0, t);
    stA(As[0], fa, t);
    stB(Bs2[0], fb, t);

    int cur = 0;
    for (int tt = 0; tt < 2 * TILES; tt++) {
        __syncthreads();
        bool has_next = (tt + 1 < 2 * TILES);
        if (has_next) {
            int nt = tt + 1;
            int p  = (nt >= TILES);
            int k0 = (nt - (p ? TILES : 0)) * 16;
            ldA(fa, p ? g_agg0 : x,      rowBase, k0, t);
            ldB(fb, p ? Wneigh : Wself,  colBase, k0, t);
        }
        // compute on buffer `cur`
        #pragma unroll
        for (int k = 0; k < 16; k++) {
            const unsigned long long* a64 =
                reinterpret_cast<const unsigned long long*>(&As[cur][k][ty * 8]);
            const unsigned long long* b64 =
                reinterpret_cast<const unsigned long long*>(&Bs2[cur][k][tx * 16]);
            unsigned long long a2[4], b2[8];
            #pragma unroll
            for (int i = 0; i < 4; i++) a2[i] = a64[i];
            #pragma unroll
            for (int j = 0; j < 8; j++) b2[j] = b64[j];
            #pragma unroll
            for (int i = 0; i < 4; i++)
                #pragma unroll
                for (int j = 0; j < 8; j++)
                    FMA2(acc[i][j], a2[i], b2[j]);
        }
        if (has_next) {
            stA(As[cur ^ 1], fa, t);
            stB(Bs2[cur ^ 1], fb, t);
        }
        cur ^= 1;
    }

    // epilogue: unpack pairs, + bias, relu, store
    float bias[8];
    #pragma unroll
    for (int j = 0; j < 8; j++) bias[j] = __ldg(&b0[colBase + tx * 8 + j]);

    #pragma unroll
    for (int i2 = 0; i2 < 4; i2++) {
        int r0 = rowBase + ty * 8 + i2 * 2;
        float lo[8], hi[8];
        #pragma unroll
        for (int j = 0; j < 8; j++) {
            unsigned long long v = acc[i2][j];
            lo[j] = fmaxf(__uint_as_float((unsigned)(v & 0xffffffffull)) + bias[j], 0.f);
            hi[j] = fmaxf(__uint_as_float((unsigned)(v >> 32))           + bias[j], 0.f);
        }
        int c = colBase + tx * 8;
        if (r0 < N_DST0) {
            float4* p = reinterpret_cast<float4*>(&g_h[(size_t)r0 * F_HID + c]);
            p[0] = make_float4(lo[0], lo[1], lo[2], lo[3]);
            p[1] = make_float4(lo[4], lo[5], lo[6], lo[7]);
        }
        if (r0 + 1 < N_DST0) {
            float4* p = reinterpret_cast<float4*>(&g_h[(size_t)(r0 + 1) * F_HID + c]);
            p[0] = make_float4(hi[0], hi[1], hi[2], hi[3]);
            p[1] = make_float4(hi[4], hi[5], hi[6], hi[7]);
        }
    }
}

// ---------------- layer-1 scatter: one warp per edge ---------------------------
__global__ void k_scatter1(const int* __restrict__ src,
                           const int* __restrict__ dst) {
    int gthread = blockIdx.x * blockDim.x + threadIdx.x;
    int warp = gthread >> 5;
    int lane = threadIdx.x & 31;
    if (warp >= N_E1) return;
    int s = src[warp];
    int d = dst[warp];
    const float2* hs = (const float2*)(g_h + (size_t)s * F_HID);
    float*        ag = g_agg1 + (size_t)d * F_HID;
    #pragma unroll
    for (int f = lane; f < F_HID / 2; f += 32) {
        float2 v = hs[f];
        atomicAdd(ag + 2*f,     v.x);
        atomicAdd(ag + 2*f + 1, v.y);
    }
    if (lane == 0) atomicAdd(&g_cnt1[d], 1.f);
}

__global__ void k_scale1() {
    int i  = blockIdx.x * blockDim.x + threadIdx.x;
    int st = gridDim.x * blockDim.x;
    for (int j = i; j < N_DST1 * F_HID; j += st) {
        int row = j >> 8;
        float c = g_cnt1[row];
        g_agg1[j] *= 1.f / fmaxf(c, 1.f);
    }
}

// ---------------- output GEMM: one block per row -------------------------------
__global__ void __launch_bounds__(64)
k_out(const float* __restrict__ Ws1,
      const float* __restrict__ Wn1,
      const float* __restrict__ b1,
      float* __restrict__ out) {
    __shared__ float hs[F_HID];
    __shared__ float as[F_HID];
    int row = blockIdx.x;
    int t = threadIdx.x;
    reinterpret_cast<float4*>(hs)[t] =
        reinterpret_cast<const float4*>(g_h + (size_t)row * F_HID)[t];
    reinterpret_cast<float4*>(as)[t] =
        reinterpret_cast<const float4*>(g_agg1 + (size_t)row * F_HID)[t];
    __syncthreads();
    if (t < F_OUT) {
        float acc = __ldg(&b1[t]);
        #pragma unroll 8
        for (int k = 0; k < F_HID; k++) {
            acc += hs[k] * __ldg(&Ws1[k * F_OUT + t]);
            acc += as[k] * __ldg(&Wn1[k * F_OUT + t]);
        }
        out[row * F_OUT + t] = acc;
    }
}

// ---------------- launch ------------------------------------------------------
extern "C" void kernel_launch(void* const* d_in, const int* in_sizes, int n_in,
                              void* d_out, int out_size) {
    const float* x      = (const float*)d_in[0];
    const float* Wself0 = (const float*)d_in[1];
    const float* Wneigh0= (const float*)d_in[2];
    const float* b0     = (const float*)d_in[3];
    const float* Wself1 = (const float*)d_in[4];
    const float* Wneigh1= (const float*)d_in[5];
    const float* b1     = (const float*)d_in[6];
    const int*   e0_src = (const int*)d_in[7];
    const int*   e0_dst = (const int*)d_in[8];
    const int*   e1_src = (const int*)d_in[9];
    const int*   e1_dst = (const int*)d_in[10];
    float* out = (float*)d_out;

    // 1. zero scratch
    k_zero_scratch<<<1024, 256>>>();

    // 2. layer-0 scatter-add (one warp per edge)
    {
        int blocks = (N_E0 * 32 + 255) / 256;
        k_scatter0<<<blocks, 256>>>(x, e0_src, e0_dst);
    }

    // 3. mean
    k_scale0<<<2048, 256>>>();

    // 4. fused layer-0 GEMM + relu (f32x2 packed)
    {
        dim3 grid(F_HID / 64, (N_DST0 + 63) / 64);   // (4, 172) = 688 blocks
        k_gemm0<<<grid, 64>>>(x, Wself0, Wneigh0, b0);
    }

    // 5. layer-1 scatter-add
    {
        int blocks = (N_E1 * 32 + 255) / 256;
        k_scatter1<<<blocks, 256>>>(e1_src, e1_dst);
    }

    // 6. mean
    k_scale1<<<256, 256>>>();

    // 7. output GEMM
    k_out<<<N_DST1, 64>>>(Wself1, Wneigh1, b1, out);
}

// round 3
// speedup vs baseline: 1.9311x; 1.9125x over previous
#include <cuda_runtime.h>
#include <cstdint>

#define N_SRC0 286000
#define N_DST0 11000
#define N_E0   275000
#define N_DST1 1000
#define N_E1   10000
#define F_IN   602
#define F_HID  256
#define F_OUT  41

// ---------------- scratch (static device globals; no allocation) -------------
__device__ float g_agg0[(size_t)N_DST0 * F_IN + 8];
__device__ float g_cnt0[N_DST0];
__device__ float g_h   [(size_t)N_DST0 * F_HID];
__device__ float g_agg1[(size_t)N_DST1 * F_HID];
__device__ float g_cnt1[N_DST1];

// ---------------- zero scratch ------------------------------------------------
__global__ void k_zero() {
    int i  = blockIdx.x * blockDim.x + threadIdx.x;
    int st = gridDim.x * blockDim.x;
    for (int j = i; j < N_DST0 * F_IN;  j += st) g_agg0[j] = 0.f;
    for (int j = i; j < N_DST0;         j += st) g_cnt0[j] = 0.f;
    for (int j = i; j < N_DST1 * F_HID; j += st) g_agg1[j] = 0.f;
    for (int j = i; j < N_DST1;         j += st) g_cnt1[j] = 0.f;
}

// ---------------- layer-0 scatter: one warp per edge --------------------------
__global__ void k_scatter0(const float* __restrict__ x,
                           const int* __restrict__ src,
                           const int* __restrict__ dst) {
    int gthread = blockIdx.x * blockDim.x + threadIdx.x;
    int warp = gthread >> 5;
    int lane = threadIdx.x & 31;
    if (warp >= N_E0) return;
    int s = src[warp];
    int d = dst[warp];
    const float2* xs = (const float2*)(x + (size_t)s * F_IN);
    float*        ag = g_agg0 + (size_t)d * F_IN;
    const int NF2 = F_IN / 2;  // 301
    #pragma unroll 4
    for (int f = lane; f < NF2; f += 32) {
        float2 v = __ldg(xs + f);
        atomicAdd(ag + 2*f,     v.x);
        atomicAdd(ag + 2*f + 1, v.y);
    }
    if (lane == 0) atomicAdd(&g_cnt0[d], 1.f);
}

// =============================================================================
// layer-0 GEMM via tf32 mma.sync  (M=11000, N=256, K=2x602)
// h = relu([x[:N_DST0] | agg0/cnt] @ [Wself0; Wneigh0] + b0)
// block: 128 thr (2x2 warps), BM=128 BN=64 BK=16; warp tile 64x32 (m16n8k8)
// A staged in smem in fragment layout; B fragments loaded gmem->reg (L2 hits)
// =============================================================================

__device__ __forceinline__ uint32_t f2tf(float f) {
    uint32_t r; asm("cvt.rna.tf32.f32 %0, %1;" : "=r"(r) : "f"(f)); return r;
}

#define MMA_TF32(c, a, br0, br1)                                          \
    asm volatile("mma.sync.aligned.m16n8k8.row.col.f32.tf32.tf32.f32 "   \
        "{%0,%1,%2,%3}, {%4,%5,%6,%7}, {%8,%9}, {%0,%1,%2,%3};"          \
        : "+f"(c[0]), "+f"(c[1]), "+f"(c[2]), "+f"(c[3])                  \
        : "r"(a[0]), "r"(a[1]), "r"(a[2]), "r"(a[3]), "r"(br0), "r"(br1))

struct AStage { float v[4][4]; };

// gather one 128x16 A tile into registers (zero-fill OOB, optional row-scale)
__device__ __forceinline__ void lda(AStage& s, const float* __restrict__ base,
                                    int rowBase, int lm, int kq, int k0,
                                    bool scale, const float* invc) {
    #pragma unroll
    for (int p = 0; p < 4; p++) {
        int gm = rowBase + p * 32 + lm;
        int gk = k0 + kq * 4;
        float2 v0 = make_float2(0.f, 0.f), v1 = make_float2(0.f, 0.f);
        if (gm < N_DST0) {
            const float* rp = base + (size_t)gm * F_IN;
            if (gk < F_IN)     v0 = __ldg((const float2*)(rp + gk));
            if (gk + 2 < F_IN) v1 = __ldg((const float2*)(rp + gk + 2));
        }
        float sc = scale ? invc[p] : 1.f;
        s.v[p][0] = v0.x * sc; s.v[p][1] = v0.y * sc;
        s.v[p][2] = v1.x * sc; s.v[p][3] = v1.y * sc;
    }
}

// store staged A into fragment-layout smem: As[mt][k8][reg][lane]
__device__ __forceinline__ void sta(uint32_t (*As)[2][4][32], const AStage& s,
                                    int lm, int kq) {
    int k8 = kq >> 1;
    #pragma unroll
    for (int p = 0; p < 4; p++) {
        int m   = p * 32 + lm;
        int mt  = m >> 4;
        int reg = ((m >> 3) & 1) + ((kq & 1) << 1);
        int lb  = (m & 7) * 4;
        uint4 w;
        w.x = f2tf(s.v[p][0]); w.y = f2tf(s.v[p][1]);
        w.z = f2tf(s.v[p][2]); w.w = f2tf(s.v[p][3]);
        *(uint4*)&As[mt][k8][reg][lb] = w;
    }
}

// load B fragments for one 16-k tile straight from gmem (16 regs)
__device__ __forceinline__ void ldb(uint32_t* b, const float* __restrict__ W,
                                    int k0, int cb, int tig, int gid) {
    #pragma unroll
    for (int k8 = 0; k8 < 2; k8++)
        #pragma unroll
        for (int nt = 0; nt < 4; nt++)
            #pragma unroll
            for (int r = 0; r < 2; r++) {
                int k = k0 + k8 * 8 + r * 4 + tig;
                int c = cb + nt * 8 + gid;
                float v = (k < F_IN) ? __ldg(&W[(size_t)k * F_HID + c]) : 0.f;
                b[(k8 * 4 + nt) * 2 + r] = f2tf(v);
            }
}

__device__ __forceinline__ void compute_tile(const uint32_t (*As)[2][4][32],
                                             const uint32_t* b,
                                             float acc[4][4][4],
                                             int wm, int lane) {
    #pragma unroll
    for (int k8 = 0; k8 < 2; k8++) {
        uint32_t a[4][4];
        #pragma unroll
        for (int mt = 0; mt < 4; mt++)
            #pragma unroll
            for (int r = 0; r < 4; r++)
                a[mt][r] = As[wm * 4 + mt][k8][r][lane];
        #pragma unroll
        for (int mt = 0; mt < 4; mt++)
            #pragma unroll
            for (int nt = 0; nt < 4; nt++)
                MMA_TF32(acc[mt][nt], a[mt],
                         b[(k8 * 4 + nt) * 2], b[(k8 * 4 + nt) * 2 + 1]);
    }
}

__global__ void __launch_bounds__(128, 3)
k_gemm0(const float* __restrict__ x,
        const float* __restrict__ Wself,
        const float* __restrict__ Wneigh,
        const float* __restrict__ b0) {
    __shared__ __align__(16) uint32_t As[2][8][2][4][32];  // 16 KB

    const int t    = threadIdx.x;
    const int warp = t >> 5, lane = t & 31;
    const int wm = warp & 1, wn = warp >> 1;
    const int gid = lane >> 2, tig = lane & 3;
    const int rowBase = blockIdx.y * 128;
    const int colBase = blockIdx.x * 64;
    const int lm = t >> 2;      // loader row-in-pass (0..31)
    const int kq = t & 3;       // loader k quad

    // cached inverse counts for the 4 rows this thread loads (agg half)
    float invc[4];
    #pragma unroll
    for (int p = 0; p < 4; p++) {
        int gm = rowBase + p * 32 + lm;
        invc[p] = (gm < N_DST0) ? (1.f / fmaxf(g_cnt0[gm], 1.f)) : 0.f;
    }

    float acc[4][4][4];
    #pragma unroll
    for (int i = 0; i < 4; i++)
        #pragma unroll
        for (int j = 0; j < 4; j++)
            #pragma unroll
            for (int r = 0; r < 4; r++) acc[i][j][r] = 0.f;

    const int HT = 38;            // tiles per half (ceil 602/16)
    const int TILES = 2 * HT;
    const int cb = colBase + wn * 32;

    AStage st;
    uint32_t bC[16], bN[16];

    lda(st, x, rowBase, lm, kq, 0, false, invc);
    ldb(bC, Wself, 0, cb, tig, gid);
    sta(As[0], st, lm, kq);
    __syncthreads();

    int buf = 0;
    for (int tile = 0; tile < TILES; tile++) {
        bool more = (tile + 1 < TILES);
        if (more) {
            int nt  = tile + 1;
            int h   = (nt >= HT);
            int k0  = (nt - (h ? HT : 0)) * 16;
            lda(st, h ? g_agg0 : x, rowBase, lm, kq, k0, h, invc);
            ldb(bN, h ? Wneigh : Wself, k0, cb, tig, gid);
        }
        compute_tile(As[buf], bC, acc, wm, lane);
        if (more) {
            sta(As[buf ^ 1], st, lm, kq);
            __syncthreads();
            buf ^= 1;
            #pragma unroll
            for (int i = 0; i < 16; i++) bC[i] = bN[i];
        }
    }

    // epilogue: bias + relu + store
    #pragma unroll
    for (int mt = 0; mt < 4; mt++) {
        int r0 = rowBase + wm * 64 + mt * 16 + gid;
        int r1 = r0 + 8;
        #pragma unroll
        for (int nt = 0; nt < 4; nt++) {
            int c = cb + nt * 8 + tig * 2;
            float bb0 = __ldg(&b0[c]);
            float bb1 = __ldg(&b0[c + 1]);
            if (r0 < N_DST0) {
                float2 v = make_float2(fmaxf(acc[mt][nt][0] + bb0, 0.f),
                                       fmaxf(acc[mt][nt][1] + bb1, 0.f));
                *(float2*)&g_h[(size_t)r0 * F_HID + c] = v;
            }
            if (r1 < N_DST0) {
                float2 v = make_float2(fmaxf(acc[mt][nt][2] + bb0, 0.f),
                                       fmaxf(acc[mt][nt][3] + bb1, 0.f));
                *(float2*)&g_h[(size_t)r1 * F_HID + c] = v;
            }
        }
    }
}

// ---------------- layer-1 scatter: one warp per edge ---------------------------
__global__ void k_scatter1(const int* __restrict__ src,
                           const int* __restrict__ dst) {
    int gthread = blockIdx.x * blockDim.x + threadIdx.x;
    int warp = gthread >> 5;
    int lane = threadIdx.x & 31;
    if (warp >= N_E1) return;
    int s = src[warp];
    int d = dst[warp];
    const float2* hs = (const float2*)(g_h + (size_t)s * F_HID);
    float*        ag = g_agg1 + (size_t)d * F_HID;
    #pragma unroll
    for (int f = lane; f < F_HID / 2; f += 32) {
        float2 v = hs[f];
        atomicAdd(ag + 2*f,     v.x);
        atomicAdd(ag + 2*f + 1, v.y);
    }
    if (lane == 0) atomicAdd(&g_cnt1[d], 1.f);
}

// ---------------- output GEMM: one block per row (mean folded in) -------------
__global__ void __launch_bounds__(64)
k_out(const float* __restrict__ Ws1,
      const float* __restrict__ Wn1,
      const float* __restrict__ b1,
      float* __restrict__ out) {
    __shared__ float hs[F_HID];
    __shared__ float as[F_HID];
    int row = blockIdx.x;
    int t = threadIdx.x;
    float inv = 1.f / fmaxf(g_cnt1[row], 1.f);
    float4 hv = ((const float4*)(g_h    + (size_t)row * F_HID))[t];
    float4 av = ((const float4*)(g_agg1 + (size_t)row * F_HID))[t];
    av.x *= inv; av.y *= inv; av.z *= inv; av.w *= inv;
    ((float4*)hs)[t] = hv;
    ((float4*)as)[t] = av;
    __syncthreads();
    if (t < F_OUT) {
        float acc = __ldg(&b1[t]);
        #pragma unroll 8
        for (int k = 0; k < F_HID; k++) {
            acc += hs[k] * __ldg(&Ws1[k * F_OUT + t]);
            acc += as[k] * __ldg(&Wn1[k * F_OUT + t]);
        }
        out[row * F_OUT + t] = acc;
    }
}

// ---------------- launch ------------------------------------------------------
extern "C" void kernel_launch(void* const* d_in, const int* in_sizes, int n_in,
                              void* d_out, int out_size) {
    const float* x      = (const float*)d_in[0];
    const float* Wself0 = (const float*)d_in[1];
    const float* Wneigh0= (const float*)d_in[2];
    const float* b0     = (const float*)d_in[3];
    const float* Wself1 = (const float*)d_in[4];
    const float* Wneigh1= (const float*)d_in[5];
    const float* b1     = (const float*)d_in[6];
    const int*   e0_src = (const int*)d_in[7];
    const int*   e0_dst = (const int*)d_in[8];
    const int*   e1_src = (const int*)d_in[9];
    const int*   e1_dst = (const int*)d_in[10];
    float* out = (float*)d_out;

    k_zero<<<2048, 256>>>();

    {
        int blocks = (N_E0 * 32 + 255) / 256;
        k_scatter0<<<blocks, 256>>>(x, e0_src, e0_dst);
    }

    {
        dim3 grid(F_HID / 64, (N_DST0 + 127) / 128);   // (4, 86) = 344 blocks
        k_gemm0<<<grid, 128>>>(x, Wself0, Wneigh0, b0);
    }

    {
        int blocks = (N_E1 * 32 + 255) / 256;
        k_scatter1<<<blocks, 256>>>(e1_src, e1_dst);
    }

    k_out<<<N_DST1, 64>>>(Wself1, Wneigh1, b1, out);
}

// round 4
// speedup vs baseline: 2.4048x; 1.2453x over previous
#include <cuda_runtime.h>
#include <cstdint>

#define N_SRC0 286000
#define N_DST0 11000
#define N_E0   275000
#define N_DST1 1000
#define N_E1   10000
#define F_IN   602
#define F_HID  256
#define F_OUT  41

// ---------------- scratch (static device globals; no allocation) -------------
__device__ float g_agg0[(size_t)N_DST0 * F_IN + 8];
__device__ float g_h   [(size_t)N_DST0 * F_HID];
__device__ float g_agg1[(size_t)N_DST1 * F_HID];
__device__ float g_cnt1[N_DST1];
// CSR build for layer-0 edges
__device__ int   g_deg0[N_DST0];
__device__ int   g_cur0[N_DST0];
__device__ int   g_off0[N_DST0 + 1];
__device__ int   g_eidx[N_E0];

// ---------------- zero small scratch ------------------------------------------
__global__ void k_zero() {
    int i  = blockIdx.x * blockDim.x + threadIdx.x;
    int st = gridDim.x * blockDim.x;
    for (int j = i; j < N_DST0; j += st) { g_deg0[j] = 0; g_cur0[j] = 0; }
    for (int j = i; j < N_DST1 * F_HID; j += st) g_agg1[j] = 0.f;
    for (int j = i; j < N_DST1; j += st) g_cnt1[j] = 0.f;
}

// ---------------- CSR build ----------------------------------------------------
__global__ void k_hist(const int* __restrict__ dst) {
    int i = blockIdx.x * blockDim.x + threadIdx.x;
    if (i < N_E0) atomicAdd(&g_deg0[dst[i]], 1);
}

__global__ void __launch_bounds__(1024)
k_prefix() {
    __shared__ int sh[1024];
    __shared__ int carry;
    int t = threadIdx.x;
    if (t == 0) carry = 0;
    __syncthreads();
    for (int base = 0; base < N_DST0; base += 1024) {
        int v = (base + t < N_DST0) ? g_deg0[base + t] : 0;
        sh[t] = v;
        __syncthreads();
        #pragma unroll
        for (int ofs = 1; ofs < 1024; ofs <<= 1) {
            int add = (t >= ofs) ? sh[t - ofs] : 0;
            __syncthreads();
            sh[t] += add;
            __syncthreads();
        }
        if (base + t < N_DST0) g_off0[base + t] = carry + sh[t] - v;
        int tot = sh[1023];
        __syncthreads();
        if (t == 0) carry += tot;
        __syncthreads();
    }
    if (t == 0) g_off0[N_DST0] = carry;
}

__global__ void k_fill(const int* __restrict__ src, const int* __restrict__ dst) {
    int i = blockIdx.x * blockDim.x + threadIdx.x;
    if (i < N_E0) {
        int d = dst[i];
        int p = atomicAdd(&g_cur0[d], 1);
        g_eidx[g_off0[d] + p] = src[i];
    }
}

// ---------------- layer-0 mean aggregation: pull (one block per dst) ----------
__global__ void __launch_bounds__(256)
k_agg0(const float* __restrict__ x) {
    int d = blockIdx.x;
    int t = threadIdx.x;
    int beg = g_off0[d], end = g_off0[d + 1];
    int deg = end - beg;

    int f0 = t, f1 = t + 256, f2 = t + 512;
    bool has2 = (f2 < F_IN);          // t < 90
    float a0 = 0.f, a1 = 0.f, a2 = 0.f;

    int e = beg;
    for (; e + 1 < end; e += 2) {
        int s0 = __ldg(&g_eidx[e]);
        int s1 = __ldg(&g_eidx[e + 1]);
        const float* r0 = x + (size_t)s0 * F_IN;
        const float* r1 = x + (size_t)s1 * F_IN;
        float u0 = __ldg(r0 + f0), v0 = __ldg(r1 + f0);
        float u1 = __ldg(r0 + f1), v1 = __ldg(r1 + f1);
        float u2 = 0.f, v2 = 0.f;
        if (has2) { u2 = __ldg(r0 + f2); v2 = __ldg(r1 + f2); }
        a0 += u0 + v0; a1 += u1 + v1; a2 += u2 + v2;
    }
    if (e < end) {
        int s0 = __ldg(&g_eidx[e]);
        const float* r0 = x + (size_t)s0 * F_IN;
        a0 += __ldg(r0 + f0);
        a1 += __ldg(r0 + f1);
        if (has2) a2 += __ldg(r0 + f2);
    }

    float inv = (deg > 0) ? (1.f / (float)deg) : 0.f;
    float* o = g_agg0 + (size_t)d * F_IN;
    o[f0] = a0 * inv;
    o[f1] = a1 * inv;
    if (has2) o[f2] = a2 * inv;
}

// =============================================================================
// layer-0 GEMM via tf32 mma.sync  (M=11000, N=256, K=2x602)
// h = relu([x[:N_DST0] | agg0] @ [Wself0; Wneigh0] + b0)
// =============================================================================

__device__ __forceinline__ uint32_t f2tf(float f) {
    uint32_t r; asm("cvt.rna.tf32.f32 %0, %1;" : "=r"(r) : "f"(f)); return r;
}

#define MMA_TF32(c, a, br0, br1)                                          \
    asm volatile("mma.sync.aligned.m16n8k8.row.col.f32.tf32.tf32.f32 "   \
        "{%0,%1,%2,%3}, {%4,%5,%6,%7}, {%8,%9}, {%0,%1,%2,%3};"          \
        : "+f"(c[0]), "+f"(c[1]), "+f"(c[2]), "+f"(c[3])                  \
        : "r"(a[0]), "r"(a[1]), "r"(a[2]), "r"(a[3]), "r"(br0), "r"(br1))

struct AStage { float v[4][4]; };

__device__ __forceinline__ void lda(AStage& s, const float* __restrict__ base,
                                    int rowBase, int lm, int kq, int k0) {
    #pragma unroll
    for (int p = 0; p < 4; p++) {
        int gm = rowBase + p * 32 + lm;
        int gk = k0 + kq * 4;
        float2 v0 = make_float2(0.f, 0.f), v1 = make_float2(0.f, 0.f);
        if (gm < N_DST0) {
            const float* rp = base + (size_t)gm * F_IN;
            if (gk < F_IN)     v0 = __ldg((const float2*)(rp + gk));
            if (gk + 2 < F_IN) v1 = __ldg((const float2*)(rp + gk + 2));
        }
        s.v[p][0] = v0.x; s.v[p][1] = v0.y;
        s.v[p][2] = v1.x; s.v[p][3] = v1.y;
    }
}

__device__ __forceinline__ void sta(uint32_t (*As)[2][4][32], const AStage& s,
                                    int lm, int kq) {
    int k8 = kq >> 1;
    #pragma unroll
    for (int p = 0; p < 4; p++) {
        int m   = p * 32 + lm;
        int mt  = m >> 4;
        int reg = ((m >> 3) & 1) + ((kq & 1) << 1);
        int lb  = (m & 7) * 4;
        uint4 w;
        w.x = f2tf(s.v[p][0]); w.y = f2tf(s.v[p][1]);
        w.z = f2tf(s.v[p][2]); w.w = f2tf(s.v[p][3]);
        *(uint4*)&As[mt][k8][reg][lb] = w;
    }
}

__device__ __forceinline__ void ldb(uint32_t* b, const float* __restrict__ W,
                                    int k0, int cb, int tig, int gid) {
    #pragma unroll
    for (int k8 = 0; k8 < 2; k8++)
        #pragma unroll
        for (int nt = 0; nt < 4; nt++)
            #pragma unroll
            for (int r = 0; r < 2; r++) {
                int k = k0 + k8 * 8 + r * 4 + tig;
                int c = cb + nt * 8 + gid;
                float v = (k < F_IN) ? __ldg(&W[(size_t)k * F_HID + c]) : 0.f;
                b[(k8 * 4 + nt) * 2 + r] = f2tf(v);
            }
}

__device__ __forceinline__ void compute_tile(const uint32_t (*As)[2][4][32],
                                             const uint32_t* b,
                                             float acc[4][4][4],
                                             int wm, int lane) {
    #pragma unroll
    for (int k8 = 0; k8 < 2; k8++) {
        uint32_t a[4][4];
        #pragma unroll
        for (int mt = 0; mt < 4; mt++)
            #pragma unroll
            for (int r = 0; r < 4; r++)
                a[mt][r] = As[wm * 4 + mt][k8][r][lane];
        #pragma unroll
        for (int mt = 0; mt < 4; mt++)
            #pragma unroll
            for (int nt = 0; nt < 4; nt++)
                MMA_TF32(acc[mt][nt], a[mt],
                         b[(k8 * 4 + nt) * 2], b[(k8 * 4 + nt) * 2 + 1]);
    }
}

__global__ void __launch_bounds__(128, 3)
k_gemm0(const float* __restrict__ x,
        const float* __restrict__ Wself,
        const float* __restrict__ Wneigh,
        const float* __restrict__ b0) {
    __shared__ __align__(16) uint32_t As[2][8][2][4][32];  // 16 KB

    const int t    = threadIdx.x;
    const int warp = t >> 5, lane = t & 31;
    const int wm = warp & 1, wn = warp >> 1;
    const int gid = lane >> 2, tig = lane & 3;
    const int rowBase = blockIdx.y * 128;
    const int colBase = blockIdx.x * 64;
    const int lm = t >> 2;
    const int kq = t & 3;

    float acc[4][4][4];
    #pragma unroll
    for (int i = 0; i < 4; i++)
        #pragma unroll
        for (int j = 0; j < 4; j++)
            #pragma unroll
            for (int r = 0; r < 4; r++) acc[i][j][r] = 0.f;

    const int HT = 38;
    const int TILES = 2 * HT;
    const int cb = colBase + wn * 32;

    AStage st;
    uint32_t bC[16], bN[16];

    lda(st, x, rowBase, lm, kq, 0);
    ldb(bC, Wself, 0, cb, tig, gid);
    sta(As[0], st, lm, kq);
    __syncthreads();

    int buf = 0;
    for (int tile = 0; tile < TILES; tile++) {
        bool more = (tile + 1 < TILES);
        if (more) {
            int nt  = tile + 1;
            int h   = (nt >= HT);
            int k0  = (nt - (h ? HT : 0)) * 16;
            lda(st, h ? g_agg0 : x, rowBase, lm, kq, k0);
            ldb(bN, h ? Wneigh : Wself, k0, cb, tig, gid);
        }
        compute_tile(As[buf], bC, acc, wm, lane);
        if (more) {
            sta(As[buf ^ 1], st, lm, kq);
            __syncthreads();
            buf ^= 1;
            #pragma unroll
            for (int i = 0; i < 16; i++) bC[i] = bN[i];
        }
    }

    #pragma unroll
    for (int mt = 0; mt < 4; mt++) {
        int r0 = rowBase + wm * 64 + mt * 16 + gid;
        int r1 = r0 + 8;
        #pragma unroll
        for (int nt = 0; nt < 4; nt++) {
            int c = cb + nt * 8 + tig * 2;
            float bb0 = __ldg(&b0[c]);
            float bb1 = __ldg(&b0[c + 1]);
            if (r0 < N_DST0) {
                float2 v = make_float2(fmaxf(acc[mt][nt][0] + bb0, 0.f),
                                       fmaxf(acc[mt][nt][1] + bb1, 0.f));
                *(float2*)&g_h[(size_t)r0 * F_HID + c] = v;
            }
            if (r1 < N_DST0) {
                float2 v = make_float2(fmaxf(acc[mt][nt][2] + bb0, 0.f),
                                       fmaxf(acc[mt][nt][3] + bb1, 0.f));
                *(float2*)&g_h[(size_t)r1 * F_HID + c] = v;
            }
        }
    }
}

// ---------------- layer-1 scatter: one warp per edge ---------------------------
__global__ void k_scatter1(const int* __restrict__ src,
                           const int* __restrict__ dst) {
    int gthread = blockIdx.x * blockDim.x + threadIdx.x;
    int warp = gthread >> 5;
    int lane = threadIdx.x & 31;
    if (warp >= N_E1) return;
    int s = src[warp];
    int d = dst[warp];
    const float2* hs = (const float2*)(g_h + (size_t)s * F_HID);
    float*        ag = g_agg1 + (size_t)d * F_HID;
    #pragma unroll
    for (int f = lane; f < F_HID / 2; f += 32) {
        float2 v = hs[f];
        atomicAdd(ag + 2*f,     v.x);
        atomicAdd(ag + 2*f + 1, v.y);
    }
    if (lane == 0) atomicAdd(&g_cnt1[d], 1.f);
}

// ---------------- output GEMM: one block per row (mean folded in) -------------
__global__ void __launch_bounds__(64)
k_out(const float* __restrict__ Ws1,
      const float* __restrict__ Wn1,
      const float* __restrict__ b1,
      float* __restrict__ out) {
    __shared__ float hs[F_HID];
    __shared__ float as[F_HID];
    int row = blockIdx.x;
    int t = threadIdx.x;
    float inv = 1.f / fmaxf(g_cnt1[row], 1.f);
    float4 hv = ((const float4*)(g_h    + (size_t)row * F_HID))[t];
    float4 av = ((const float4*)(g_agg1 + (size_t)row * F_HID))[t];
    av.x *= inv; av.y *= inv; av.z *= inv; av.w *= inv;
    ((float4*)hs)[t] = hv;
    ((float4*)as)[t] = av;
    __syncthreads();
    if (t < F_OUT) {
        float acc = __ldg(&b1[t]);
        #pragma unroll 8
        for (int k = 0; k < F_HID; k++) {
            acc += hs[k] * __ldg(&Ws1[k * F_OUT + t]);
            acc += as[k] * __ldg(&Wn1[k * F_OUT + t]);
        }
        out[row * F_OUT + t] = acc;
    }
}

// ---------------- launch ------------------------------------------------------
extern "C" void kernel_launch(void* const* d_in, const int* in_sizes, int n_in,
                              void* d_out, int out_size) {
    const float* x      = (const float*)d_in[0];
    const float* Wself0 = (const float*)d_in[1];
    const float* Wneigh0= (const float*)d_in[2];
    const float* b0     = (const float*)d_in[3];
    const float* Wself1 = (const float*)d_in[4];
    const float* Wneigh1= (const float*)d_in[5];
    const float* b1     = (const float*)d_in[6];
    const int*   e0_src = (const int*)d_in[7];
    const int*   e0_dst = (const int*)d_in[8];
    const int*   e1_src = (const int*)d_in[9];
    const int*   e1_dst = (const int*)d_in[10];
    float* out = (float*)d_out;

    k_zero<<<256, 256>>>();
    k_hist<<<(N_E0 + 255) / 256, 256>>>(e0_dst);
    k_prefix<<<1, 1024>>>();
    k_fill<<<(N_E0 + 255) / 256, 256>>>(e0_src, e0_dst);
    k_agg0<<<N_DST0, 256>>>(x);

    {
        dim3 grid(F_HID / 64, (N_DST0 + 127) / 128);   // (4, 86)
        k_gemm0<<<grid, 128>>>(x, Wself0, Wneigh0, b0);
    }

    {
        int blocks = (N_E1 * 32 + 255) / 256;
        k_scatter1<<<blocks, 256>>>(e1_src, e1_dst);
    }

    k_out<<<N_DST1, 64>>>(Wself1, Wneigh1, b1, out);
}